// round 8
// baseline (speedup 1.0000x reference)
#include <cuda_runtime.h>

// ---------------------------------------------------------------------------
// RobustStateSpaceSimulatorAugmented — two-phase, XLA-arithmetic-matched fp32.
//
// Model: reference = JAX/XLA fp32. To track its trajectory bit-for-bit we:
//   * use XLA/Eigen's rational tanh approximation (NOT libdevice tanhf),
//   * accumulate every dot product with a single sequential fmaf chain in
//     ascending k order (cuBLAS SGEMM order), bias added after the dot,
//   * mirror the gamma/mu/sig expression tree op-for-op in fp32 (__f*_rn).
//
// Phase 1 (sequential, 128 CTAs x 8 rows): xf/xp/xb recurrence; pre-clip
//   states parked in d_out's own slots. Phase 2 (parallel, 16384 CTAs x 16
//   rows): y MLPs + in-place clip of the x slots at load.
// ---------------------------------------------------------------------------

#define BDIM 1024
#define TDIM 256
#define HID  512
#define HIDS 520
#define NTHR 256
#define M1   8
#define NCTA1 (BDIM / M1)
#define M2   16
#define NCTA2 ((BDIM * TDIM) / M2)

__device__ __forceinline__ float2 ffma2(float2 a, float2 b, float2 c) {
#if __CUDA_ARCH__ >= 1000
    union U { float2 f; unsigned long long u; };
    U A, B, C, D;
    A.f = a; B.f = b; C.f = c;
    asm("fma.rn.f32x2 %0, %1, %2, %3;" : "=l"(D.u) : "l"(A.u), "l"(B.u), "l"(C.u));
    return D.f;
#else
    return make_float2(fmaf(a.x, b.x, c.x), fmaf(a.y, b.y, c.y));
#endif
}

__device__ __forceinline__ float clipf(float v, float lo, float hi) {
    return fminf(fmaxf(v, lo), hi);
}

// XLA/Eigen/MLIR fast-tanh for f32: clamp, tiny passthrough, rational 13/6.
// Exact FMA sequence of the reference emitter.
__device__ __forceinline__ float xla_tanh(float x) {
    const float c = 7.99881172180175781f;
    float xc = fminf(fmaxf(x, -c), c);
    float x2 = __fmul_rn(xc, xc);
    float p = fmaf(x2, -2.76076847742355e-16f, 2.00018790482477e-13f);
    p = fmaf(x2, p, -8.60467152213735e-11f);
    p = fmaf(x2, p, 5.12229709037114e-08f);
    p = fmaf(x2, p, 1.48572235717979e-05f);
    p = fmaf(x2, p, 6.37261928875436e-04f);
    p = fmaf(x2, p, 4.89352455891786e-03f);
    p = __fmul_rn(xc, p);
    float q = fmaf(x2, 1.19825839466702e-06f, 1.18534705686654e-04f);
    q = fmaf(x2, q, 2.26843463243900e-03f);
    q = fmaf(x2, q, 4.89352518554385e-03f);
    float r = __fdiv_rn(p, q);
    return (fabsf(x) < 0.0004f) ? x : r;
}

// ---- layer 1: ONE sequential fmaf chain per (row, hidden unit) ------------
// Each float2 lane is an independent strictly-sequential ascending-k chain.

template<int N, int S, int M>
__device__ __forceinline__ void l1_accum(float2* acc,
                                         const float* __restrict__ W1,
                                         const float* __restrict__ x, int j0)
{
#pragma unroll 4
    for (int k = 0; k < N; k += 4) {
        float2 w0 = *reinterpret_cast<const float2*>(W1 + (k + 0) * HID + j0);
        float2 w1 = *reinterpret_cast<const float2*>(W1 + (k + 1) * HID + j0);
        float2 w2 = *reinterpret_cast<const float2*>(W1 + (k + 2) * HID + j0);
        float2 w3 = *reinterpret_cast<const float2*>(W1 + (k + 3) * HID + j0);
#pragma unroll
        for (int r = 0; r < M; r++) {
            float4 xv = *reinterpret_cast<const float4*>(x + r * S + k);
            acc[r] = ffma2(w0, make_float2(xv.x, xv.x), acc[r]);
            acc[r] = ffma2(w1, make_float2(xv.y, xv.y), acc[r]);
            acc[r] = ffma2(w2, make_float2(xv.z, xv.z), acc[r]);
            acc[r] = ffma2(w3, make_float2(xv.w, xv.w), acc[r]);
        }
    }
}

// hidden = xla_tanh(dot + b1); thread owns hidden pair (2*tid).
template<int N0, int S0, int N1, int S1, int N2, int S2, int M>
__device__ __forceinline__ void mlp_l1(const float* __restrict__ W1,
                                       const float* __restrict__ b1,
                                       const float* __restrict__ x0,
                                       const float* __restrict__ x1,
                                       const float* __restrict__ x2,
                                       float* __restrict__ hid, int tid)
{
    const int j0 = 2 * tid;
    float2 acc[M];
#pragma unroll
    for (int r = 0; r < M; r++) acc[r] = make_float2(0.f, 0.f);

    l1_accum<N0, S0, M>(acc, W1, x0, j0);
    l1_accum<N1, S1, M>(acc, W1 + N0 * HID, x1, j0);
    if constexpr (N2 > 0)
        l1_accum<N2, S2, M>(acc, W1 + (N0 + N1) * HID, x2, j0);

    float2 bv = *reinterpret_cast<const float2*>(b1 + j0);
#pragma unroll
    for (int r = 0; r < M; r++) {
        float sx = __fadd_rn(acc[r].x, bv.x);   // bias AFTER full dot
        float sy = __fadd_rn(acc[r].y, bv.y);
        *reinterpret_cast<float2*>(hid + r * HIDS + j0) =
            make_float2(xla_tanh(sx), xla_tanh(sy));
    }
}

// ---- layer 2: ONE sequential fmaf chain per (row, output) -----------------
// DOUT*M==512 -> thread owns an output PAIR; DOUT*M==256 -> a single output.
// No j-split, no partial reduction: exact cuBLAS-style sequential order.

template<int DOUT, int M, bool ACC>
__device__ __forceinline__ void mlp_l2(const float* __restrict__ W2,
                                       const float* __restrict__ b2,
                                       const float* __restrict__ hid,
                                       float* __restrict__ out, int tid)
{
    static_assert(DOUT * M == 512 || DOUT * M == 256, "bad l2 shape");
    if constexpr (DOUT * M == 512) {
        constexpr int PAIRS = DOUT / 2;
        const int op = tid % PAIRS;
        const int r  = tid / PAIRS;
        const float* hrow = hid + r * HIDS;
        const float* wp   = W2 + 2 * op;
        float2 acc = make_float2(0.f, 0.f);
#pragma unroll 4
        for (int j = 0; j < HID; j += 4) {
            float4 hv = *reinterpret_cast<const float4*>(hrow + j);
            acc = ffma2(*reinterpret_cast<const float2*>(wp + (j + 0) * DOUT), make_float2(hv.x, hv.x), acc);
            acc = ffma2(*reinterpret_cast<const float2*>(wp + (j + 1) * DOUT), make_float2(hv.y, hv.y), acc);
            acc = ffma2(*reinterpret_cast<const float2*>(wp + (j + 2) * DOUT), make_float2(hv.z, hv.z), acc);
            acc = ffma2(*reinterpret_cast<const float2*>(wp + (j + 3) * DOUT), make_float2(hv.w, hv.w), acc);
        }
        float2 bv = *reinterpret_cast<const float2*>(b2 + 2 * op);
        float sx = __fadd_rn(acc.x, bv.x);
        float sy = __fadd_rn(acc.y, bv.y);
        float* o = out + r * DOUT + 2 * op;
        if constexpr (ACC) { o[0] = __fadd_rn(o[0], sx); o[1] = __fadd_rn(o[1], sy); }
        else               { o[0] = sx; o[1] = sy; }
    } else {
        const int o = tid % DOUT;
        const int r = tid / DOUT;
        const float* hrow = hid + r * HIDS;
        float acc = 0.f;
#pragma unroll 4
        for (int j = 0; j < HID; j += 4) {
            float4 hv = *reinterpret_cast<const float4*>(hrow + j);
            acc = fmaf(hv.x, W2[(j + 0) * DOUT + o], acc);
            acc = fmaf(hv.y, W2[(j + 1) * DOUT + o], acc);
            acc = fmaf(hv.z, W2[(j + 2) * DOUT + o], acc);
            acc = fmaf(hv.w, W2[(j + 3) * DOUT + o], acc);
        }
        float s = __fadd_rn(acc, b2[o]);
        float* op_ = out + r * DOUT + o;
        if constexpr (ACC) *op_ = __fadd_rn(*op_, s); else *op_ = s;
    }
}

// ---------------------------------------------------------------------------
// Phase 1: sequential recurrence (fp32 mirror of the reference)
// ---------------------------------------------------------------------------

struct __align__(16) SmemSeq {
    float xf  [M1 * 64];
    float xp  [M1 * 64];
    float xb  [M1 * 32];
    float mu  [M1 * 32];
    float sig [M1 * 32];
    float thf [M1 * 8];
    float u   [M1 * 16];
    float dxp [M1 * 64];
    float dxfb[M1 * 64];
    float gbv [M1 * 32];
    float hid [M1 * HIDS];
};

__global__ void __launch_bounds__(NTHR, 1)
seq_kernel(const float* __restrict__ xf0,  const float* __restrict__ xb0,
           const float* __restrict__ u,    const float* __restrict__ thf_g,
           const float* __restrict__ fW1,  const float* __restrict__ fb1,
           const float* __restrict__ fW2,  const float* __restrict__ fb2,
           const float* __restrict__ fbW1, const float* __restrict__ fbb1,
           const float* __restrict__ fbW2, const float* __restrict__ fbb2,
           const float* __restrict__ gbW1, const float* __restrict__ gbb1,
           const float* __restrict__ gbW2, const float* __restrict__ gbb2,
           const float* __restrict__ xlo_p, const float* __restrict__ xhi_p,
           const float* __restrict__ xblo_p, const float* __restrict__ xbhi_p,
           float* __restrict__ out)
{
    __shared__ SmemSeq sm;
    const int tid = threadIdx.x;
    const int R0  = blockIdx.x * M1;

    const float xlo  = *xlo_p,  xhi  = *xhi_p;
    const float xblo = *xblo_p, xbhi = *xbhi_p;

    float* out_xf = out;
    float* out_xb = out + (size_t)BDIM * TDIM * 64;
    float* out_xp = out + (size_t)BDIM * TDIM * (64 + 32 + 16);

    const int er = tid >> 5, ei = tid & 31;   // NTHR == M1*32

    // ---- init: t=0 records = raw carry0 ----
    for (int idx = tid; idx < M1 * 64; idx += NTHR) {
        int r = idx >> 6, i = idx & 63;
        float v = xf0[(size_t)(R0 + r) * 64 + i];
        sm.xf[idx] = v; sm.xp[idx] = v;
        size_t go = ((size_t)(R0 + r) * TDIM) * 64 + i;
        out_xf[go] = v; out_xp[go] = v;
    }
    {
        float v = xb0[(size_t)(R0 + er) * 32 + ei];
        sm.xb[tid] = v;
        sm.mu[tid] = 0.f; sm.sig[tid] = 1.f;
        out_xb[((size_t)(R0 + er) * TDIM) * 32 + ei] = v;
    }
    if (tid < M1 * 8) {
        int r = tid >> 3, i = tid & 7;
        sm.thf[tid] = thf_g[(size_t)(R0 + r) * 8 + i];
    }
    __syncthreads();

    // ---- recurrence: iterations t = 0..T-2 produce records at t+1 ----
    for (int t = 0; t < TDIM - 1; t++) {
        const float tf  = (float)t;
        const float t1f = tf + 1.f, t2f = tf + 2.f;
        const float q21 = __fdiv_rn(t2f, t1f);               // (t+2)/(t+1)
        const float r12 = __fdiv_rn(t1f, t2f);               // (t+1)/(t+2)
        const float it2 = __fdiv_rn(1.f, t2f);               // 1/(t+2)
        const float c4  = __fdiv_rn(__fmul_rn(2.f, __fmul_rn(t2f, t2f)), t1f);

        if (tid < M1 * 16) {
            int r = tid >> 4, i = tid & 15;
            sm.u[tid] = u[((size_t)(R0 + r) * TDIM + t) * 16 + i];
        }
        __syncthreads();

        // g_b(xp, xb, u) -> gbv[32]
        mlp_l1<64, 64, 32, 32, 16, 16, M1>(gbW1, gbb1, sm.xp, sm.xb, sm.u, sm.hid, tid);
        __syncthreads();
        mlp_l2<32, M1, false>(gbW2, gbb2, sm.hid, sm.gbv, tid);
        __syncthreads();

        // f(xp, u, theta_f) -> dxp[64]
        mlp_l1<64, 64, 16, 16, 8, 8, M1>(fW1, fb1, sm.xp, sm.u, sm.thf, sm.hid, tid);
        __syncthreads();
        mlp_l2<64, M1, false>(fW2, fb2, sm.hid, sm.dxp, tid);
        __syncthreads();

        // f_b(xp, xb, u) -> dxfb[64]
        mlp_l1<64, 64, 32, 32, 16, 16, M1>(fbW1, fbb1, sm.xp, sm.xb, sm.u, sm.hid, tid);
        __syncthreads();
        mlp_l2<64, M1, false>(fbW2, fbb2, sm.hid, sm.dxfb, tid);
        __syncthreads();

        const int tt = t + 1;

        // xp_n / xf_n: PRE-CLIP -> out buffer; clipped -> SMEM state
        for (int idx = tid; idx < M1 * 64; idx += NTHR) {
            int r = idx >> 6, i = idx & 63;
            float dxp  = sm.dxp[idx];
            float dxfb = sm.dxfb[idx];
            float xpn  = __fadd_rn(sm.xp[idx], dxp);
            float dxf  = __fadd_rn(dxp, dxfb);          // reference ordering
            float xfn  = __fadd_rn(sm.xf[idx], dxf);
            size_t go = ((size_t)(R0 + r) * TDIM + tt) * 64 + i;
            out_xp[go] = xpn;                           // pre-clip
            out_xf[go] = xfn;                           // pre-clip
            sm.xp[idx] = clipf(xpn, xlo, xhi);
            sm.xf[idx] = clipf(xfn, xlo, xhi);
        }

        // gamma chain — exact fp32 mirror of the reference expression tree
        {
            float gbv = sm.gbv[tid];
            float xb  = sm.xb[tid];
            float mu  = sm.mu[tid];
            float sig = sm.sig[tid];

            float gp   = sig;                            // sig ** 1
            float igp  = __fdiv_rn(1.f, gp);
            float opig = __fadd_rn(1.f, igp);            // 1 + 1/gp
            float xmm  = __fsub_rn(xb, mu);

            float hg   = __fmul_rn(gbv, 0.5f);           // gbv/2 (exact)
            float d1   = __fmul_rn(gbv, __fadd_rn(xmm, __fmul_rn(hg, opig)));
            float d2   = __fsub_rn(1.f, igp);
            float delta = __fmul_rn(d1, d2);

            float sig2 = __fmul_rn(sig, sig);
            float epsA = __fmul_rn(t2f, __fsub_rn(sig2, q21));
            float gp2  = __fmul_rn(gp, gp);
            float igp2 = __fdiv_rn(1.f, gp2);
            float gbv2h = __fmul_rn(__fmul_rn(gbv, gbv), 0.5f);
            float termA = __fadd_rn(xmm, __fmul_rn(gbv, opig));
            float termB = __fmul_rn(gbv2h, __fadd_rn(1.f, igp2));
            float eps  = __fadd_rn(epsA, __fmul_rn(xmm, __fadd_rn(termA, termB)));

            float d2e2 = __fsub_rn(__fmul_rn(delta, delta), __fmul_rn(eps, eps));
            bool D1 = (eps >= delta) && (delta >= 0.f);
            bool D2 = (eps <  delta) && (delta <  0.f);
            bool D3 = (delta < eps)  && (eps   <  0.f);
            bool D4 = (__fmul_rn(c4, eps) >= d2e2) && (d2e2 > 0.f);
            bool sel = D1 || D2 || D3 || D4;

            float xbn = sel ? __fdiv_rn(gbv, gp) : gbv;  // gbv / gamma

            out_xb[((size_t)(R0 + er) * TDIM + tt) * 32 + ei] = xbn; // pre-clip

            float xbc = clipf(xbn, xblo, xbhi);
            sm.xb[tid] = xbc;

            float mun = __fadd_rn(__fmul_rn(r12, mu), __fmul_rn(it2, xbc));
            float dd  = __fsub_rn(xbc, mun);
            float s2  = __fadd_rn(__fmul_rn(r12, __fmul_rn(sig, sig)),
                                  __fmul_rn(it2, __fmul_rn(dd, dd)));
            sm.mu[tid]  = mun;
            sm.sig[tid] = sqrtf(s2);
        }
        __syncthreads();
    }
}

// ---------------------------------------------------------------------------
// Phase 2: y = h(xp_n, theta_h) + h_b(xf_n, xb_n); x slots clipped in-place
// at load time (t==0 rows hold the raw initial carry, recorded unclipped).
// ---------------------------------------------------------------------------

struct __align__(16) SmemY {
    float xpn[M2 * 64];
    float xfn[M2 * 64];
    float xbn[M2 * 32];
    float thh[M2 * 8];
    float y  [M2 * 16];
    float hid[M2 * HIDS];
};

__global__ void __launch_bounds__(NTHR, 1)
y_kernel(const float* __restrict__ thh_g,
         const float* __restrict__ hW1,  const float* __restrict__ hb1,
         const float* __restrict__ hW2,  const float* __restrict__ hb2,
         const float* __restrict__ hbW1, const float* __restrict__ hbb1,
         const float* __restrict__ hbW2, const float* __restrict__ hbb2,
         const float* __restrict__ xlo_p, const float* __restrict__ xhi_p,
         const float* __restrict__ xblo_p, const float* __restrict__ xbhi_p,
         const float* __restrict__ ylo_p, const float* __restrict__ yhi_p,
         float* __restrict__ out)
{
    __shared__ SmemY sm;
    const int tid = threadIdx.x;
    const int G0  = blockIdx.x * M2;   // global row (b*T + t)

    const float xlo  = *xlo_p,  xhi  = *xhi_p;
    const float xblo = *xblo_p, xbhi = *xbhi_p;
    const float ylo  = *ylo_p,  yhi  = *yhi_p;

    float* out_xf = out;
    float* out_xb = out + (size_t)BDIM * TDIM * 64;
    float* out_y  = out + (size_t)BDIM * TDIM * (64 + 32);
    float* out_xp = out + (size_t)BDIM * TDIM * (64 + 32 + 16);

    for (int idx = tid; idx < M2 * 64; idx += NTHR) {
        int r = idx >> 6, i = idx & 63;
        int gi = G0 + r;
        size_t go = (size_t)gi * 64 + i;
        float xp = out_xp[go], xf = out_xf[go];
        sm.xpn[idx] = xp;
        sm.xfn[idx] = xf;
        if ((gi & (TDIM - 1)) != 0) {
            out_xp[go] = clipf(xp, xlo, xhi);
            out_xf[go] = clipf(xf, xlo, xhi);
        }
    }
    for (int idx = tid; idx < M2 * 32; idx += NTHR) {
        int r = idx >> 5, i = idx & 31;
        int gi = G0 + r;
        size_t go = (size_t)gi * 32 + i;
        float xb = out_xb[go];
        sm.xbn[idx] = xb;
        if ((gi & (TDIM - 1)) != 0)
            out_xb[go] = clipf(xb, xblo, xbhi);
    }
    if (tid < M2 * 8) {
        int r = tid >> 3, i = tid & 7;
        int b = (G0 + r) >> 8;   // TDIM == 256
        sm.thh[tid] = thh_g[(size_t)b * 8 + i];
    }
    __syncthreads();

    mlp_l1<64, 64, 8, 8, 0, 0, M2>(hW1, hb1, sm.xpn, sm.thh, nullptr, sm.hid, tid);
    __syncthreads();
    mlp_l2<16, M2, false>(hW2, hb2, sm.hid, sm.y, tid);
    __syncthreads();
    mlp_l1<64, 64, 32, 32, 0, 0, M2>(hbW1, hbb1, sm.xfn, sm.xbn, nullptr, sm.hid, tid);
    __syncthreads();
    mlp_l2<16, M2, true>(hbW2, hbb2, sm.hid, sm.y, tid);
    __syncthreads();

    if (tid < M2 * 16) {
        int r = tid >> 4, i = tid & 15;
        int gi = G0 + r;
        float v = sm.y[tid];
        if ((gi & (TDIM - 1)) != 0) v = clipf(v, ylo, yhi);  // y0 unclipped
        out_y[(size_t)gi * 16 + i] = v;
    }
}

extern "C" void kernel_launch(void* const* d_in, const int* in_sizes, int n_in,
                              void* d_out, int out_size) {
    (void)in_sizes; (void)n_in; (void)out_size;
    const float* xf0  = (const float*)d_in[0];
    const float* xb0  = (const float*)d_in[1];
    const float* uu   = (const float*)d_in[2];
    const float* thf  = (const float*)d_in[3];
    const float* thh  = (const float*)d_in[4];
    const float* fW1  = (const float*)d_in[5];
    const float* fb1  = (const float*)d_in[6];
    const float* fW2  = (const float*)d_in[7];
    const float* fb2  = (const float*)d_in[8];
    const float* fbW1 = (const float*)d_in[9];
    const float* fbb1 = (const float*)d_in[10];
    const float* fbW2 = (const float*)d_in[11];
    const float* fbb2 = (const float*)d_in[12];
    const float* gbW1 = (const float*)d_in[13];
    const float* gbb1 = (const float*)d_in[14];
    const float* gbW2 = (const float*)d_in[15];
    const float* gbb2 = (const float*)d_in[16];
    const float* hW1  = (const float*)d_in[17];
    const float* hb1  = (const float*)d_in[18];
    const float* hW2  = (const float*)d_in[19];
    const float* hb2  = (const float*)d_in[20];
    const float* hbW1 = (const float*)d_in[21];
    const float* hbb1 = (const float*)d_in[22];
    const float* hbW2 = (const float*)d_in[23];
    const float* hbb2 = (const float*)d_in[24];
    const float* xlo  = (const float*)d_in[25];
    const float* xhi  = (const float*)d_in[26];
    const float* xblo = (const float*)d_in[27];
    const float* xbhi = (const float*)d_in[28];
    const float* ylo  = (const float*)d_in[29];
    const float* yhi  = (const float*)d_in[30];
    float* out = (float*)d_out;

    seq_kernel<<<NCTA1, NTHR>>>(xf0, xb0, uu, thf,
                                fW1, fb1, fW2, fb2,
                                fbW1, fbb1, fbW2, fbb2,
                                gbW1, gbb1, gbW2, gbb2,
                                xlo, xhi, xblo, xbhi, out);
    y_kernel<<<NCTA2, NTHR>>>(thh, hW1, hb1, hW2, hb2,
                              hbW1, hbb1, hbW2, hbb2,
                              xlo, xhi, xblo, xbhi, ylo, yhi, out);
}

// round 10
// speedup vs baseline: 1.1076x; 1.1076x over previous
#include <cuda_runtime.h>

// ---------------------------------------------------------------------------
// RobustStateSpaceSimulatorAugmented — two-phase, XLA-arithmetic-matched fp32.
//
// Numerics (validated R8, rel_err 2.1e-4): XLA/Eigen rational tanh, strictly
// sequential ascending-k fmaf chains per output (cuBLAS order), bias added
// after the dot, gamma/mu/sig mirrored op-for-op in fp32.
//
// R9 perf change: seq_kernel runs 512 threads (4 warps/SMSP) to hide the
// L2 weight-load latency that dominated R8 (75k cyc/step vs 15k issue floor).
//  - layer-1: two 256-thread halves each own 4 of the 8 rows (bit-identical
//    chains; duplicate weight loads hit L1D).
//  - layer-2: one SCALAR sequential chain per (row, output) over 512 threads
//    (identical numerics to a packed-lane chain), unroll 8 for deep prefetch.
// ---------------------------------------------------------------------------

#define BDIM 1024
#define TDIM 256
#define HID  512
#define HIDS 520
#define M1   8
#define NTHR1 512
#define NCTA1 (BDIM / M1)
#define M2   16
#define NTHR2 256
#define NCTA2 ((BDIM * TDIM) / M2)

__device__ __forceinline__ float2 ffma2(float2 a, float2 b, float2 c) {
#if __CUDA_ARCH__ >= 1000
    union U { float2 f; unsigned long long u; };
    U A, B, C, D;
    A.f = a; B.f = b; C.f = c;
    asm("fma.rn.f32x2 %0, %1, %2, %3;" : "=l"(D.u) : "l"(A.u), "l"(B.u), "l"(C.u));
    return D.f;
#else
    return make_float2(fmaf(a.x, b.x, c.x), fmaf(a.y, b.y, c.y));
#endif
}

__device__ __forceinline__ float clipf(float v, float lo, float hi) {
    return fminf(fmaxf(v, lo), hi);
}

// XLA/Eigen/MLIR fast-tanh for f32 (exact FMA sequence of the emitter).
__device__ __forceinline__ float xla_tanh(float x) {
    const float c = 7.99881172180175781f;
    float xc = fminf(fmaxf(x, -c), c);
    float x2 = __fmul_rn(xc, xc);
    float p = fmaf(x2, -2.76076847742355e-16f, 2.00018790482477e-13f);
    p = fmaf(x2, p, -8.60467152213735e-11f);
    p = fmaf(x2, p, 5.12229709037114e-08f);
    p = fmaf(x2, p, 1.48572235717979e-05f);
    p = fmaf(x2, p, 6.37261928875436e-04f);
    p = fmaf(x2, p, 4.89352455891786e-03f);
    p = __fmul_rn(xc, p);
    float q = fmaf(x2, 1.19825839466702e-06f, 1.18534705686654e-04f);
    q = fmaf(x2, q, 2.26843463243900e-03f);
    q = fmaf(x2, q, 4.89352518554385e-03f);
    float r = __fdiv_rn(p, q);
    return (fabsf(x) < 0.0004f) ? x : r;
}

// ---- layer 1: one sequential chain per (row, hidden pair lane) ------------

template<int N, int S, int M>
__device__ __forceinline__ void l1_accum(float2* acc,
                                         const float* __restrict__ W1,
                                         const float* __restrict__ x, int j0)
{
#pragma unroll 4
    for (int k = 0; k < N; k += 4) {
        float2 w0 = *reinterpret_cast<const float2*>(W1 + (k + 0) * HID + j0);
        float2 w1 = *reinterpret_cast<const float2*>(W1 + (k + 1) * HID + j0);
        float2 w2 = *reinterpret_cast<const float2*>(W1 + (k + 2) * HID + j0);
        float2 w3 = *reinterpret_cast<const float2*>(W1 + (k + 3) * HID + j0);
#pragma unroll
        for (int r = 0; r < M; r++) {
            float4 xv = *reinterpret_cast<const float4*>(x + r * S + k);
            acc[r] = ffma2(w0, make_float2(xv.x, xv.x), acc[r]);
            acc[r] = ffma2(w1, make_float2(xv.y, xv.y), acc[r]);
            acc[r] = ffma2(w2, make_float2(xv.z, xv.z), acc[r]);
            acc[r] = ffma2(w3, make_float2(xv.w, xv.w), acc[r]);
        }
    }
}

// hidden = xla_tanh(dot + b1). jt = this thread's hidden-pair index;
// x0/x1/x2/hid already offset to this thread-group's first row.
template<int N0, int S0, int N1, int S1, int N2, int S2, int M>
__device__ __forceinline__ void mlp_l1(const float* __restrict__ W1,
                                       const float* __restrict__ b1,
                                       const float* __restrict__ x0,
                                       const float* __restrict__ x1,
                                       const float* __restrict__ x2,
                                       float* __restrict__ hid, int jt)
{
    const int j0 = 2 * jt;
    float2 acc[M];
#pragma unroll
    for (int r = 0; r < M; r++) acc[r] = make_float2(0.f, 0.f);

    l1_accum<N0, S0, M>(acc, W1, x0, j0);
    l1_accum<N1, S1, M>(acc, W1 + N0 * HID, x1, j0);
    if constexpr (N2 > 0)
        l1_accum<N2, S2, M>(acc, W1 + (N0 + N1) * HID, x2, j0);

    float2 bv = *reinterpret_cast<const float2*>(b1 + j0);
#pragma unroll
    for (int r = 0; r < M; r++) {
        float sx = __fadd_rn(acc[r].x, bv.x);   // bias AFTER full dot
        float sy = __fadd_rn(acc[r].y, bv.y);
        *reinterpret_cast<float2*>(hid + r * HIDS + j0) =
            make_float2(xla_tanh(sx), xla_tanh(sy));
    }
}

// ---- layer 2 (seq): one SCALAR sequential chain per (row, output) ---------
// Thread t -> (o = t % DOUT, r = t / DOUT); threads with r >= ROWS idle.

template<int DOUT, int ROWS, int NT>
__device__ __forceinline__ void l2_seq(const float* __restrict__ W2,
                                       const float* __restrict__ b2,
                                       const float* __restrict__ hid,
                                       float* __restrict__ out, int tid)
{
    const int o = tid % DOUT;
    const int r = tid / DOUT;
    if (DOUT * ROWS >= NT || r < ROWS) {
        const float* hrow = hid + r * HIDS;
        float acc = 0.f;
#pragma unroll 8
        for (int j = 0; j < HID; j += 4) {
            float4 hv = *reinterpret_cast<const float4*>(hrow + j);
            acc = fmaf(hv.x, W2[(j + 0) * DOUT + o], acc);
            acc = fmaf(hv.y, W2[(j + 1) * DOUT + o], acc);
            acc = fmaf(hv.z, W2[(j + 2) * DOUT + o], acc);
            acc = fmaf(hv.w, W2[(j + 3) * DOUT + o], acc);
        }
        out[r * DOUT + o] = __fadd_rn(acc, b2[o]);
    }
}

// ---- layer 2 (y): scalar chain per (row, output), optional accumulate -----

template<int DOUT, int M, bool ACC>
__device__ __forceinline__ void l2_y(const float* __restrict__ W2,
                                     const float* __restrict__ b2,
                                     const float* __restrict__ hid,
                                     float* __restrict__ out, int tid)
{
    static_assert(DOUT * M == 256, "y l2 shape");
    const int o = tid % DOUT;
    const int r = tid / DOUT;
    const float* hrow = hid + r * HIDS;
    float acc = 0.f;
#pragma unroll 8
    for (int j = 0; j < HID; j += 4) {
        float4 hv = *reinterpret_cast<const float4*>(hrow + j);
        acc = fmaf(hv.x, W2[(j + 0) * DOUT + o], acc);
        acc = fmaf(hv.y, W2[(j + 1) * DOUT + o], acc);
        acc = fmaf(hv.z, W2[(j + 2) * DOUT + o], acc);
        acc = fmaf(hv.w, W2[(j + 3) * DOUT + o], acc);
    }
    float s = __fadd_rn(acc, b2[o]);
    float* op_ = out + r * DOUT + o;
    if constexpr (ACC) *op_ = __fadd_rn(*op_, s); else *op_ = s;
}

// ---------------------------------------------------------------------------
// Phase 1: sequential recurrence, 512 threads (two row-halves of 4)
// ---------------------------------------------------------------------------

struct __align__(16) SmemSeq {
    float xf  [M1 * 64];
    float xp  [M1 * 64];
    float xb  [M1 * 32];
    float mu  [M1 * 32];
    float sig [M1 * 32];
    float thf [M1 * 8];
    float u   [M1 * 16];
    float dxp [M1 * 64];
    float dxfb[M1 * 64];
    float gbv [M1 * 32];
    float hid [M1 * HIDS];
};

__global__ void __launch_bounds__(NTHR1, 1)
seq_kernel(const float* __restrict__ xf0,  const float* __restrict__ xb0,
           const float* __restrict__ u,    const float* __restrict__ thf_g,
           const float* __restrict__ fW1,  const float* __restrict__ fb1,
           const float* __restrict__ fW2,  const float* __restrict__ fb2,
           const float* __restrict__ fbW1, const float* __restrict__ fbb1,
           const float* __restrict__ fbW2, const float* __restrict__ fbb2,
           const float* __restrict__ gbW1, const float* __restrict__ gbb1,
           const float* __restrict__ gbW2, const float* __restrict__ gbb2,
           const float* __restrict__ xlo_p, const float* __restrict__ xhi_p,
           const float* __restrict__ xblo_p, const float* __restrict__ xbhi_p,
           float* __restrict__ out)
{
    __shared__ SmemSeq sm;
    const int tid  = threadIdx.x;
    const int half = tid >> 8;          // 0 -> rows 0..3, 1 -> rows 4..7
    const int ht   = tid & 255;         // hidden-pair index within half

    const int R0  = blockIdx.x * M1;

    const float xlo  = *xlo_p,  xhi  = *xhi_p;
    const float xblo = *xblo_p, xbhi = *xbhi_p;

    float* out_xf = out;
    float* out_xb = out + (size_t)BDIM * TDIM * 64;
    float* out_xp = out + (size_t)BDIM * TDIM * (64 + 32 + 16);

    const int er = tid >> 5, ei = tid & 31;   // valid for tid < 256

    // ---- init: t=0 records = raw carry0 ----
    for (int idx = tid; idx < M1 * 64; idx += NTHR1) {
        int r = idx >> 6, i = idx & 63;
        float v = xf0[(size_t)(R0 + r) * 64 + i];
        sm.xf[idx] = v; sm.xp[idx] = v;
        size_t go = ((size_t)(R0 + r) * TDIM) * 64 + i;
        out_xf[go] = v; out_xp[go] = v;
    }
    if (tid < M1 * 32) {
        float v = xb0[(size_t)(R0 + er) * 32 + ei];
        sm.xb[tid] = v;
        sm.mu[tid] = 0.f; sm.sig[tid] = 1.f;
        out_xb[((size_t)(R0 + er) * TDIM) * 32 + ei] = v;
    }
    if (tid < M1 * 8) {
        int r = tid >> 3, i = tid & 7;
        sm.thf[tid] = thf_g[(size_t)(R0 + r) * 8 + i];
    }
    __syncthreads();

    // ---- recurrence: iterations t = 0..T-2 produce records at t+1 ----
    for (int t = 0; t < TDIM - 1; t++) {
        const float tf  = (float)t;
        const float t1f = tf + 1.f, t2f = tf + 2.f;
        const float q21 = __fdiv_rn(t2f, t1f);
        const float r12 = __fdiv_rn(t1f, t2f);
        const float it2 = __fdiv_rn(1.f, t2f);
        const float c4  = __fdiv_rn(__fmul_rn(2.f, __fmul_rn(t2f, t2f)), t1f);

        if (tid < M1 * 16) {
            int r = tid >> 4, i = tid & 15;
            sm.u[tid] = u[((size_t)(R0 + r) * TDIM + t) * 16 + i];
        }
        __syncthreads();

        // g_b(xp, xb, u) -> gbv[32]
        mlp_l1<64, 64, 32, 32, 16, 16, 4>(gbW1, gbb1,
            sm.xp + half * 4 * 64, sm.xb + half * 4 * 32, sm.u + half * 4 * 16,
            sm.hid + half * 4 * HIDS, ht);
        __syncthreads();
        l2_seq<32, M1, NTHR1>(gbW2, gbb2, sm.hid, sm.gbv, tid);
        __syncthreads();

        // f(xp, u, theta_f) -> dxp[64]
        mlp_l1<64, 64, 16, 16, 8, 8, 4>(fW1, fb1,
            sm.xp + half * 4 * 64, sm.u + half * 4 * 16, sm.thf + half * 4 * 8,
            sm.hid + half * 4 * HIDS, ht);
        __syncthreads();
        l2_seq<64, M1, NTHR1>(fW2, fb2, sm.hid, sm.dxp, tid);
        __syncthreads();

        // f_b(xp, xb, u) -> dxfb[64]
        mlp_l1<64, 64, 32, 32, 16, 16, 4>(fbW1, fbb1,
            sm.xp + half * 4 * 64, sm.xb + half * 4 * 32, sm.u + half * 4 * 16,
            sm.hid + half * 4 * HIDS, ht);
        __syncthreads();
        l2_seq<64, M1, NTHR1>(fbW2, fbb2, sm.hid, sm.dxfb, tid);
        __syncthreads();

        const int tt = t + 1;

        // xp_n / xf_n: PRE-CLIP -> out buffer; clipped -> SMEM state
        for (int idx = tid; idx < M1 * 64; idx += NTHR1) {
            int r = idx >> 6, i = idx & 63;
            float dxp  = sm.dxp[idx];
            float dxfb = sm.dxfb[idx];
            float xpn  = __fadd_rn(sm.xp[idx], dxp);
            float dxf  = __fadd_rn(dxp, dxfb);          // reference ordering
            float xfn  = __fadd_rn(sm.xf[idx], dxf);
            size_t go = ((size_t)(R0 + r) * TDIM + tt) * 64 + i;
            out_xp[go] = xpn;                           // pre-clip
            out_xf[go] = xfn;                           // pre-clip
            sm.xp[idx] = clipf(xpn, xlo, xhi);
            sm.xf[idx] = clipf(xfn, xlo, xhi);
        }

        // gamma chain — exact fp32 mirror of the reference expression tree
        if (tid < M1 * 32) {
            float gbv = sm.gbv[tid];
            float xb  = sm.xb[tid];
            float mu  = sm.mu[tid];
            float sig = sm.sig[tid];

            float gp   = sig;                            // sig ** 1
            float igp  = __fdiv_rn(1.f, gp);
            float opig = __fadd_rn(1.f, igp);
            float xmm  = __fsub_rn(xb, mu);

            float hg   = __fmul_rn(gbv, 0.5f);
            float d1   = __fmul_rn(gbv, __fadd_rn(xmm, __fmul_rn(hg, opig)));
            float d2   = __fsub_rn(1.f, igp);
            float delta = __fmul_rn(d1, d2);

            float sig2 = __fmul_rn(sig, sig);
            float epsA = __fmul_rn(t2f, __fsub_rn(sig2, q21));
            float gp2  = __fmul_rn(gp, gp);
            float igp2 = __fdiv_rn(1.f, gp2);
            float gbv2h = __fmul_rn(__fmul_rn(gbv, gbv), 0.5f);
            float termA = __fadd_rn(xmm, __fmul_rn(gbv, opig));
            float termB = __fmul_rn(gbv2h, __fadd_rn(1.f, igp2));
            float eps  = __fadd_rn(epsA, __fmul_rn(xmm, __fadd_rn(termA, termB)));

            float d2e2 = __fsub_rn(__fmul_rn(delta, delta), __fmul_rn(eps, eps));
            bool D1 = (eps >= delta) && (delta >= 0.f);
            bool D2 = (eps <  delta) && (delta <  0.f);
            bool D3 = (delta < eps)  && (eps   <  0.f);
            bool D4 = (__fmul_rn(c4, eps) >= d2e2) && (d2e2 > 0.f);
            bool sel = D1 || D2 || D3 || D4;

            float xbn = sel ? __fdiv_rn(gbv, gp) : gbv;  // gbv / gamma

            out_xb[((size_t)(R0 + er) * TDIM + tt) * 32 + ei] = xbn; // pre-clip

            float xbc = clipf(xbn, xblo, xbhi);
            sm.xb[tid] = xbc;

            float mun = __fadd_rn(__fmul_rn(r12, mu), __fmul_rn(it2, xbc));
            float dd  = __fsub_rn(xbc, mun);
            float s2  = __fadd_rn(__fmul_rn(r12, __fmul_rn(sig, sig)),
                                  __fmul_rn(it2, __fmul_rn(dd, dd)));
            sm.mu[tid]  = mun;
            sm.sig[tid] = sqrtf(s2);
        }
        __syncthreads();
    }
}

// ---------------------------------------------------------------------------
// Phase 2: y = h(xp_n, theta_h) + h_b(xf_n, xb_n); x slots clipped in-place
// at load time (t==0 rows hold the raw initial carry, recorded unclipped).
// ---------------------------------------------------------------------------

struct __align__(16) SmemY {
    float xpn[M2 * 64];
    float xfn[M2 * 64];
    float xbn[M2 * 32];
    float thh[M2 * 8];
    float y  [M2 * 16];
    float hid[M2 * HIDS];
};

__global__ void __launch_bounds__(NTHR2, 1)
y_kernel(const float* __restrict__ thh_g,
         const float* __restrict__ hW1,  const float* __restrict__ hb1,
         const float* __restrict__ hW2,  const float* __restrict__ hb2,
         const float* __restrict__ hbW1, const float* __restrict__ hbb1,
         const float* __restrict__ hbW2, const float* __restrict__ hbb2,
         const float* __restrict__ xlo_p, const float* __restrict__ xhi_p,
         const float* __restrict__ xblo_p, const float* __restrict__ xbhi_p,
         const float* __restrict__ ylo_p, const float* __restrict__ yhi_p,
         float* __restrict__ out)
{
    __shared__ SmemY sm;
    const int tid = threadIdx.x;
    const int G0  = blockIdx.x * M2;   // global row (b*T + t)

    const float xlo  = *xlo_p,  xhi  = *xhi_p;
    const float xblo = *xblo_p, xbhi = *xbhi_p;
    const float ylo  = *ylo_p,  yhi  = *yhi_p;

    float* out_xf = out;
    float* out_xb = out + (size_t)BDIM * TDIM * 64;
    float* out_y  = out + (size_t)BDIM * TDIM * (64 + 32);
    float* out_xp = out + (size_t)BDIM * TDIM * (64 + 32 + 16);

    for (int idx = tid; idx < M2 * 64; idx += NTHR2) {
        int r = idx >> 6, i = idx & 63;
        int gi = G0 + r;
        size_t go = (size_t)gi * 64 + i;
        float xp = out_xp[go], xf = out_xf[go];
        sm.xpn[idx] = xp;
        sm.xfn[idx] = xf;
        if ((gi & (TDIM - 1)) != 0) {
            out_xp[go] = clipf(xp, xlo, xhi);
            out_xf[go] = clipf(xf, xlo, xhi);
        }
    }
    for (int idx = tid; idx < M2 * 32; idx += NTHR2) {
        int r = idx >> 5, i = idx & 31;
        int gi = G0 + r;
        size_t go = (size_t)gi * 32 + i;
        float xb = out_xb[go];
        sm.xbn[idx] = xb;
        if ((gi & (TDIM - 1)) != 0)
            out_xb[go] = clipf(xb, xblo, xbhi);
    }
    if (tid < M2 * 8) {
        int r = tid >> 3, i = tid & 7;
        int b = (G0 + r) >> 8;   // TDIM == 256
        sm.thh[tid] = thh_g[(size_t)b * 8 + i];
    }
    __syncthreads();

    mlp_l1<64, 64, 8, 8, 0, 0, M2>(hW1, hb1, sm.xpn, sm.thh, nullptr, sm.hid, tid);
    __syncthreads();
    l2_y<16, M2, false>(hW2, hb2, sm.hid, sm.y, tid);
    __syncthreads();
    mlp_l1<64, 64, 32, 32, 0, 0, M2>(hbW1, hbb1, sm.xfn, sm.xbn, nullptr, sm.hid, tid);
    __syncthreads();
    l2_y<16, M2, true>(hbW2, hbb2, sm.hid, sm.y, tid);
    __syncthreads();

    if (tid < M2 * 16) {
        int r = tid >> 4, i = tid & 15;
        int gi = G0 + r;
        float v = sm.y[tid];
        if ((gi & (TDIM - 1)) != 0) v = clipf(v, ylo, yhi);  // y0 unclipped
        out_y[(size_t)gi * 16 + i] = v;
    }
}

extern "C" void kernel_launch(void* const* d_in, const int* in_sizes, int n_in,
                              void* d_out, int out_size) {
    (void)in_sizes; (void)n_in; (void)out_size;
    const float* xf0  = (const float*)d_in[0];
    const float* xb0  = (const float*)d_in[1];
    const float* uu   = (const float*)d_in[2];
    const float* thf  = (const float*)d_in[3];
    const float* thh  = (const float*)d_in[4];
    const float* fW1  = (const float*)d_in[5];
    const float* fb1  = (const float*)d_in[6];
    const float* fW2  = (const float*)d_in[7];
    const float* fb2  = (const float*)d_in[8];
    const float* fbW1 = (const float*)d_in[9];
    const float* fbb1 = (const float*)d_in[10];
    const float* fbW2 = (const float*)d_in[11];
    const float* fbb2 = (const float*)d_in[12];
    const float* gbW1 = (const float*)d_in[13];
    const float* gbb1 = (const float*)d_in[14];
    const float* gbW2 = (const float*)d_in[15];
    const float* gbb2 = (const float*)d_in[16];
    const float* hW1  = (const float*)d_in[17];
    const float* hb1  = (const float*)d_in[18];
    const float* hW2  = (const float*)d_in[19];
    const float* hb2  = (const float*)d_in[20];
    const float* hbW1 = (const float*)d_in[21];
    const float* hbb1 = (const float*)d_in[22];
    const float* hbW2 = (const float*)d_in[23];
    const float* hbb2 = (const float*)d_in[24];
    const float* xlo  = (const float*)d_in[25];
    const float* xhi  = (const float*)d_in[26];
    const float* xblo = (const float*)d_in[27];
    const float* xbhi = (const float*)d_in[28];
    const float* ylo  = (const float*)d_in[29];
    const float* yhi  = (const float*)d_in[30];
    float* out = (float*)d_out;

    seq_kernel<<<NCTA1, NTHR1>>>(xf0, xb0, uu, thf,
                                 fW1, fb1, fW2, fb2,
                                 fbW1, fbb1, fbW2, fbb2,
                                 gbW1, gbb1, gbW2, gbb2,
                                 xlo, xhi, xblo, xbhi, out);
    y_kernel<<<NCTA2, NTHR2>>>(thh, hW1, hb1, hW2, hb2,
                               hbW1, hbb1, hbW2, hbb2,
                               xlo, xhi, xblo, xbhi, ylo, yhi, out);
}